// round 1
// baseline (speedup 1.0000x reference)
#include <cuda_runtime.h>
#include <math.h>

#define B_ROWS 32768
#define C_CLS  1000
#define EPSU   1e-6f
#define NORMF  0.031622776601683794f   // 1/sqrt(1000)

// ---- scratch (static device globals; no allocations) ----
__device__ float g_E[(size_t)B_ROWS * C_CLS];   // exp(z) unnormalized attention
__device__ float g_rowsum[B_ROWS];              // softmax denominators
__device__ float g_sums[(size_t)C_CLS * C_CLS]; // per-class masked sums
__device__ float g_count[C_CLS];                // per-class agree counts
__device__ int   g_label[B_ROWS];               // agree class or -1

// ---------------------------------------------------------------------------
__global__ void zero_kernel() {
    int i = blockIdx.x * blockDim.x + threadIdx.x;
    if (i < C_CLS * C_CLS) g_sums[i] = 0.0f;
    if (i < B_ROWS)        g_rowsum[i] = 0.0f;
    if (i < C_CLS)         g_count[i] = 0.0f;
}

// ---------------------------------------------------------------------------
// one warp per row: argmax of p_tar and p_vlm, agreement label + counts
__global__ void argmax_kernel(const float* __restrict__ p_tar,
                              const float* __restrict__ p_vlm) {
    int row  = blockIdx.x * (blockDim.x >> 5) + (threadIdx.x >> 5);
    int lane = threadIdx.x & 31;
    if (row >= B_ROWS) return;
    const float* pt = p_tar + (size_t)row * C_CLS;
    const float* pv = p_vlm + (size_t)row * C_CLS;
    float vt = -1.0f, vv = -1.0f;
    int   it = 0,     iv = 0;
    for (int k = lane; k < C_CLS; k += 32) {
        float a = pt[k]; if (a > vt) { vt = a; it = k; }
        float b = pv[k]; if (b > vv) { vv = b; iv = k; }
    }
    #pragma unroll
    for (int off = 16; off > 0; off >>= 1) {
        float ov = __shfl_down_sync(0xFFFFFFFFu, vt, off);
        int   oi = __shfl_down_sync(0xFFFFFFFFu, it, off);
        if (ov > vt || (ov == vt && oi < it)) { vt = ov; it = oi; }
        ov = __shfl_down_sync(0xFFFFFFFFu, vv, off);
        oi = __shfl_down_sync(0xFFFFFFFFu, iv, off);
        if (ov > vv || (ov == vv && oi < iv)) { vv = ov; iv = oi; }
    }
    if (lane == 0) {
        if (it == iv) { g_label[row] = it; atomicAdd(&g_count[it], 1.0f); }
        else          { g_label[row] = -1; }
    }
}

// ---------------------------------------------------------------------------
// one block per row; rows that agree scatter-add into g_sums[class]
__global__ void scatter_kernel(const float* __restrict__ p_tar) {
    int row = blockIdx.x;
    int c   = g_label[row];
    if (c < 0) return;
    const float* pt  = p_tar + (size_t)row * C_CLS;
    float*       dst = g_sums + (size_t)c * C_CLS;
    for (int k = threadIdx.x; k < C_CLS; k += blockDim.x)
        atomicAdd(&dst[k], pt[k]);
}

// ---------------------------------------------------------------------------
// bank_new = has ? a*bank + (1-a)*sums/count : bank
__global__ void bank_kernel(const float* __restrict__ bank,
                            const float* __restrict__ alpha,
                            float* __restrict__ out_bank) {
    int i = blockIdx.x * blockDim.x + threadIdx.x;
    if (i >= C_CLS * C_CLS) return;
    int   c   = i / C_CLS;
    float a   = alpha[0];
    float cnt = g_count[c];
    float b   = bank[i];
    out_bank[i] = (cnt > 0.0f) ? (a * b + (1.0f - a) * (g_sums[i] / cnt)) : b;
}

// ---------------------------------------------------------------------------
// GEMM1 (NT): Z = p_tar @ bank^T * NORM ; E = exp(Z) -> g_E ; rowsum atomics
// block tile 128x128, BK=8, 256 threads, 8x8 microtile
__global__ void __launch_bounds__(256) gemm1_kernel(const float* __restrict__ A,
                                                    const float* __restrict__ Bk) {
    __shared__ float As[8][128];
    __shared__ float Bs[8][128];
    const int bm = blockIdx.y * 128;
    const int bn = blockIdx.x * 128;
    const int t  = threadIdx.x;
    const int tx = t & 15;        // 0..15 -> N
    const int ty = t >> 4;        // 0..15 -> M
    const int lr = t >> 1;        // 0..127 row within tile for loads
    const int lk = (t & 1) * 4;   // 0 or 4

    float acc[8][8];
    #pragma unroll
    for (int i = 0; i < 8; i++)
        #pragma unroll
        for (int j = 0; j < 8; j++) acc[i][j] = 0.0f;

    const float* Aptr = A + (size_t)(bm + lr) * C_CLS + lk;
    const int jg      = bn + lr;
    const bool bval   = (jg < C_CLS);
    const float* Bptr = Bk + (size_t)(bval ? jg : 0) * C_CLS + lk;

    for (int k0 = 0; k0 < C_CLS; k0 += 8) {
        float4 a4 = *(const float4*)(Aptr + k0);
        float4 b4 = bval ? *(const float4*)(Bptr + k0)
                         : make_float4(0.f, 0.f, 0.f, 0.f);
        __syncthreads();
        As[lk + 0][lr] = a4.x; As[lk + 1][lr] = a4.y;
        As[lk + 2][lr] = a4.z; As[lk + 3][lr] = a4.w;
        Bs[lk + 0][lr] = b4.x; Bs[lk + 1][lr] = b4.y;
        Bs[lk + 2][lr] = b4.z; Bs[lk + 3][lr] = b4.w;
        __syncthreads();
        #pragma unroll
        for (int kk = 0; kk < 8; kk++) {
            float4 a0 = *(const float4*)&As[kk][ty * 8];
            float4 a1 = *(const float4*)&As[kk][ty * 8 + 4];
            float4 b0 = *(const float4*)&Bs[kk][tx * 8];
            float4 b1 = *(const float4*)&Bs[kk][tx * 8 + 4];
            float ar[8] = {a0.x, a0.y, a0.z, a0.w, a1.x, a1.y, a1.z, a1.w};
            float br[8] = {b0.x, b0.y, b0.z, b0.w, b1.x, b1.y, b1.z, b1.w};
            #pragma unroll
            for (int i = 0; i < 8; i++)
                #pragma unroll
                for (int j = 0; j < 8; j++)
                    acc[i][j] = fmaf(ar[i], br[j], acc[i][j]);
        }
    }

    #pragma unroll
    for (int i = 0; i < 8; i++) {
        int row = bm + ty * 8 + i;
        float rs = 0.0f;
        float* Erow = g_E + (size_t)row * C_CLS;
        #pragma unroll
        for (int j = 0; j < 8; j++) {
            int n = bn + tx * 8 + j;
            if (n < C_CLS) {
                float e = __expf(acc[i][j] * NORMF);
                Erow[n] = e;
                rs += e;
            }
        }
        atomicAdd(&g_rowsum[row], rs);
    }
}

// ---------------------------------------------------------------------------
// GEMM2 (NN): P = (E @ bank) / rowsum, fused uncertainty mixing -> p_mix
__global__ void __launch_bounds__(256) gemm2_kernel(const float* __restrict__ Bk,
                                                    const float* __restrict__ p_vlm,
                                                    float* __restrict__ out) {
    __shared__ float As[8][128];
    __shared__ float Bs[8][128];
    const int bm = blockIdx.y * 128;
    const int bn = blockIdx.x * 128;
    const int t  = threadIdx.x;
    const int tx = t & 15;
    const int ty = t >> 4;
    const int lr = t >> 1;
    const int lk = (t & 1) * 4;
    const int bkk = t >> 5;          // 0..7 : K row of B tile
    const int bn4 = (t & 31) * 4;    // 0..124 : N offset (x4)
    const bool bval = (bn + bn4) < C_CLS;  // bn4 mult of 4, C_CLS mult of 4

    float acc[8][8];
    #pragma unroll
    for (int i = 0; i < 8; i++)
        #pragma unroll
        for (int j = 0; j < 8; j++) acc[i][j] = 0.0f;

    const float* Aptr = g_E + (size_t)(bm + lr) * C_CLS + lk;

    for (int k0 = 0; k0 < C_CLS; k0 += 8) {
        float4 a4 = *(const float4*)(Aptr + k0);
        float4 b4 = bval ? *(const float4*)(Bk + (size_t)(k0 + bkk) * C_CLS + bn + bn4)
                         : make_float4(0.f, 0.f, 0.f, 0.f);
        __syncthreads();
        As[lk + 0][lr] = a4.x; As[lk + 1][lr] = a4.y;
        As[lk + 2][lr] = a4.z; As[lk + 3][lr] = a4.w;
        *(float4*)&Bs[bkk][bn4] = b4;
        __syncthreads();
        #pragma unroll
        for (int kk = 0; kk < 8; kk++) {
            float4 a0 = *(const float4*)&As[kk][ty * 8];
            float4 a1 = *(const float4*)&As[kk][ty * 8 + 4];
            float4 b0 = *(const float4*)&Bs[kk][tx * 8];
            float4 b1 = *(const float4*)&Bs[kk][tx * 8 + 4];
            float ar[8] = {a0.x, a0.y, a0.z, a0.w, a1.x, a1.y, a1.z, a1.w};
            float br[8] = {b0.x, b0.y, b0.z, b0.w, b1.x, b1.y, b1.z, b1.w};
            #pragma unroll
            for (int i = 0; i < 8; i++)
                #pragma unroll
                for (int j = 0; j < 8; j++)
                    acc[i][j] = fmaf(ar[i], br[j], acc[i][j]);
        }
    }

    #pragma unroll
    for (int i = 0; i < 8; i++) {
        int row = bm + ty * 8 + i;
        float inv = 1.0f / g_rowsum[row];
        #pragma unroll
        for (int j = 0; j < 8; j++) {
            int n = bn + tx * 8 + j;
            if (n < C_CLS) {
                float pt = acc[i][j] * inv;                  // p_tar_new
                float pv = p_vlm[(size_t)row * C_CLS + n];
                float eut = __expf(pt * __logf(pt + EPSU));  // exp(-u(pt))
                float euv = __expf(pv * __logf(pv + EPSU));
                out[(size_t)row * C_CLS + n] = (eut * pt + euv * pv) / (eut + euv);
            }
        }
    }
}

// ---------------------------------------------------------------------------
extern "C" void kernel_launch(void* const* d_in, const int* in_sizes, int n_in,
                              void* d_out, int out_size) {
    const float* p_tar = (const float*)d_in[0];
    const float* p_vlm = (const float*)d_in[1];
    const float* alpha = (const float*)d_in[2];
    const float* bank  = (const float*)d_in[3];
    float* out      = (float*)d_out;                       // p_mix [B,C]
    float* out_bank = out + (size_t)B_ROWS * C_CLS;        // bank_new [C,C]

    zero_kernel<<<(C_CLS * C_CLS + 255) / 256, 256>>>();
    argmax_kernel<<<B_ROWS / 8, 256>>>(p_tar, p_vlm);
    scatter_kernel<<<B_ROWS, 128>>>(p_tar);
    bank_kernel<<<(C_CLS * C_CLS + 255) / 256, 256>>>(bank, alpha, out_bank);

    dim3 gg((C_CLS + 127) / 128, B_ROWS / 128);  // (8, 256)
    gemm1_kernel<<<gg, 256>>>(p_tar, bank);
    gemm2_kernel<<<gg, 256>>>(bank, p_vlm, out);
}

// round 4
// speedup vs baseline: 4.1870x; 4.1870x over previous
#include <cuda_runtime.h>
#include <cuda_bf16.h>
#include <cstdint>
#include <math.h>

#define B_ROWS 32768
#define C_CLS  1000
#define KPAD   1024
#define EPSU   1e-6f
#define NORMF  0.031622776601683794f   // 1/sqrt(1000)

// ---------------- scratch (__device__ globals; no allocations) --------------
__device__ __nv_bfloat16 g_Abf[(size_t)B_ROWS * KPAD];  // p_tar bf16, K padded
__device__ __nv_bfloat16 g_Ebf[(size_t)B_ROWS * KPAD];  // exp(z) bf16, padded 0
__device__ __nv_bfloat16 g_Bbf1[(size_t)KPAD * KPAD];   // bank bf16   [n][k]
__device__ __nv_bfloat16 g_Bbf2[(size_t)KPAD * KPAD];   // bank^T bf16 [n][k]
__device__ float g_rowsum[B_ROWS];
__device__ float g_sums[(size_t)C_CLS * C_CLS];
__device__ float g_count[C_CLS];
__device__ int   g_label[B_ROWS];

// ---------------------------------------------------------------------------
__global__ void zero_kernel() {
    int i = blockIdx.x * blockDim.x + threadIdx.x;
    if (i < C_CLS * C_CLS) g_sums[i] = 0.0f;
    if (i < B_ROWS)        g_rowsum[i] = 0.0f;
    if (i < C_CLS)         g_count[i] = 0.0f;
}

__global__ void convA_kernel(const float* __restrict__ p_tar) {
    int i = blockIdx.x * blockDim.x + threadIdx.x;
    if (i >= B_ROWS * KPAD) return;
    int row = i >> 10, k = i & (KPAD - 1);
    g_Abf[i] = (k < C_CLS) ? __float2bfloat16(p_tar[(size_t)row * C_CLS + k])
                           : __float2bfloat16(0.0f);
}

__global__ void convB_kernel(const float* __restrict__ bank) {
    int i = blockIdx.x * blockDim.x + threadIdx.x;
    if (i >= KPAD * KPAD) return;
    int n = i >> 10, k = i & (KPAD - 1);
    bool v = (n < C_CLS) && (k < C_CLS);
    g_Bbf1[i] = v ? __float2bfloat16(bank[(size_t)n * C_CLS + k]) : __float2bfloat16(0.0f);
    g_Bbf2[i] = v ? __float2bfloat16(bank[(size_t)k * C_CLS + n]) : __float2bfloat16(0.0f);
}

__global__ void argmax_kernel(const float* __restrict__ p_tar,
                              const float* __restrict__ p_vlm) {
    int row  = blockIdx.x * (blockDim.x >> 5) + (threadIdx.x >> 5);
    int lane = threadIdx.x & 31;
    if (row >= B_ROWS) return;
    const float* pt = p_tar + (size_t)row * C_CLS;
    const float* pv = p_vlm + (size_t)row * C_CLS;
    float vt = -1.0f, vv = -1.0f;
    int   it = 0,     iv = 0;
    for (int k = lane; k < C_CLS; k += 32) {
        float a = pt[k]; if (a > vt) { vt = a; it = k; }
        float b = pv[k]; if (b > vv) { vv = b; iv = k; }
    }
    #pragma unroll
    for (int off = 16; off > 0; off >>= 1) {
        float ov = __shfl_down_sync(0xFFFFFFFFu, vt, off);
        int   oi = __shfl_down_sync(0xFFFFFFFFu, it, off);
        if (ov > vt || (ov == vt && oi < it)) { vt = ov; it = oi; }
        ov = __shfl_down_sync(0xFFFFFFFFu, vv, off);
        oi = __shfl_down_sync(0xFFFFFFFFu, iv, off);
        if (ov > vv || (ov == vv && oi < iv)) { vv = ov; iv = oi; }
    }
    if (lane == 0) {
        if (it == iv) { g_label[row] = it; atomicAdd(&g_count[it], 1.0f); }
        else          { g_label[row] = -1; }
    }
}

__global__ void scatter_kernel(const float* __restrict__ p_tar) {
    int row = blockIdx.x;
    int c   = g_label[row];
    if (c < 0) return;
    const float* pt  = p_tar + (size_t)row * C_CLS;
    float*       dst = g_sums + (size_t)c * C_CLS;
    for (int k = threadIdx.x; k < C_CLS; k += blockDim.x)
        atomicAdd(&dst[k], pt[k]);
}

__global__ void bank_kernel(const float* __restrict__ bank,
                            const float* __restrict__ alpha,
                            float* __restrict__ out_bank) {
    int i = blockIdx.x * blockDim.x + threadIdx.x;
    if (i >= C_CLS * C_CLS) return;
    int   c   = i / C_CLS;
    float a   = alpha[0];
    float cnt = g_count[c];
    float b   = bank[i];
    out_bank[i] = (cnt > 0.0f) ? (a * b + (1.0f - a) * (g_sums[i] / cnt)) : b;
}

// ---------------------------------------------------------------------------
// HMMA GEMM (NT, bf16 in / fp32 accum):  D[bm:+128, bn:+128] = A * B^T
// block 128x128, BK=32, 256 threads, 8 warps (4m x 2n), warp tile 32x64
// mode 1: A=g_Abf, B=g_Bbf1 ; e = exp(acc*NORM) -> g_Ebf + rowsum atomics
// mode 2: A=g_Ebf, B=g_Bbf2 ; pt = acc/rowsum ; uncertainty mixing -> out
#define BK   32
#define LDS  40          // smem row stride in bf16 (conflict-free ldmatrix)
#define NC   (KPAD / BK) // 32

__device__ __forceinline__ uint32_t smem_u32(const void* p) {
    uint32_t a;
    asm("{ .reg .u64 t; cvta.to.shared.u64 t, %1; cvt.u32.u64 %0, t; }"
        : "=r"(a) : "l"(p));
    return a;
}
__device__ __forceinline__ void ldmx4(uint32_t* r, uint32_t addr) {
    asm volatile("ldmatrix.sync.aligned.m8n8.x4.shared.b16 {%0,%1,%2,%3}, [%4];"
                 : "=r"(r[0]), "=r"(r[1]), "=r"(r[2]), "=r"(r[3]) : "r"(addr));
}
__device__ __forceinline__ void mma16816(float* c, const uint32_t* a,
                                         uint32_t b0, uint32_t b1) {
    asm volatile("mma.sync.aligned.m16n8k16.row.col.f32.bf16.bf16.f32 "
                 "{%0,%1,%2,%3}, {%4,%5,%6,%7}, {%8,%9}, {%0,%1,%2,%3};"
                 : "+f"(c[0]), "+f"(c[1]), "+f"(c[2]), "+f"(c[3])
                 : "r"(a[0]), "r"(a[1]), "r"(a[2]), "r"(a[3]), "r"(b0), "r"(b1));
}

__global__ void __launch_bounds__(256, 2)
gemm_mma(const float* __restrict__ p_vlm,
         float* __restrict__ out,
         int mode) {
    __shared__ alignas(16) __nv_bfloat16 sA[2][128 * LDS];
    __shared__ alignas(16) __nv_bfloat16 sB[2][128 * LDS];

    // device-side symbol selection (NEVER pass __device__ globals from host!)
    const __nv_bfloat16* __restrict__ A  = (mode == 1) ? g_Abf  : g_Ebf;
    const __nv_bfloat16* __restrict__ Bm = (mode == 1) ? g_Bbf1 : g_Bbf2;

    const int t    = threadIdx.x;
    const int wid  = t >> 5;
    const int l    = t & 31;
    const int wm   = wid >> 1;          // 0..3  -> m offset wm*32
    const int wn   = wid & 1;           // 0..1  -> n offset wn*64
    const int bm   = blockIdx.y * 128;
    const int bn   = blockIdx.x * 128;

    const uint4* gA = reinterpret_cast<const uint4*>(A);
    const uint4* gB = reinterpret_cast<const uint4*>(Bm);
    const int r0 = t >> 2, u0 = t & 3;
    const int r1 = (t + 256) >> 2, u1 = t & 3;

    float acc[2][8][4];
    #pragma unroll
    for (int mi = 0; mi < 2; mi++)
        #pragma unroll
        for (int ni = 0; ni < 8; ni++)
            #pragma unroll
            for (int k = 0; k < 4; k++) acc[mi][ni][k] = 0.0f;

    const int aRow = wm * 32 + (l & 15);
    const int aK   = (l & 16) ? 8 : 0;
    const int bRow = wn * 64 + (l & 7) + ((l & 16) ? 8 : 0);
    const int bK   = (l & 8) ? 8 : 0;

    // ---- prologue: chunk 0 -> buf 0 ----
    {
        uint4 va0 = gA[(size_t)(bm + r0) * 128 + u0];
        uint4 va1 = gA[(size_t)(bm + r1) * 128 + u1];
        uint4 vb0 = gB[(size_t)(bn + r0) * 128 + u0];
        uint4 vb1 = gB[(size_t)(bn + r1) * 128 + u1];
        *(uint4*)&sA[0][r0 * LDS + u0 * 8] = va0;
        *(uint4*)&sA[0][r1 * LDS + u1 * 8] = va1;
        *(uint4*)&sB[0][r0 * LDS + u0 * 8] = vb0;
        *(uint4*)&sB[0][r1 * LDS + u1 * 8] = vb1;
    }
    __syncthreads();

    for (int c = 0; c < NC; ++c) {
        const int buf = c & 1;
        uint4 va0, va1, vb0, vb1;
        if (c + 1 < NC) {
            const int kc = (c + 1) * (BK / 8);
            va0 = gA[(size_t)(bm + r0) * 128 + kc + u0];
            va1 = gA[(size_t)(bm + r1) * 128 + kc + u1];
            vb0 = gB[(size_t)(bn + r0) * 128 + kc + u0];
            vb1 = gB[(size_t)(bn + r1) * 128 + kc + u1];
        }

        const uint32_t baseA = smem_u32(&sA[buf][0]);
        const uint32_t baseB = smem_u32(&sB[buf][0]);
        #pragma unroll
        for (int s = 0; s < 2; ++s) {
            uint32_t af[2][4];
            #pragma unroll
            for (int mi = 0; mi < 2; mi++)
                ldmx4(af[mi], baseA + 2 * ((aRow + mi * 16) * LDS + s * 16 + aK));
            uint32_t bf[4][4];
            #pragma unroll
            for (int g = 0; g < 4; g++)
                ldmx4(bf[g], baseB + 2 * ((bRow + g * 16) * LDS + s * 16 + bK));
            #pragma unroll
            for (int mi = 0; mi < 2; mi++)
                #pragma unroll
                for (int g = 0; g < 4; g++) {
                    mma16816(acc[mi][2 * g],     af[mi], bf[g][0], bf[g][1]);
                    mma16816(acc[mi][2 * g + 1], af[mi], bf[g][2], bf[g][3]);
                }
        }

        if (c + 1 < NC) {
            const int nb = buf ^ 1;
            __syncthreads();
            *(uint4*)&sA[nb][r0 * LDS + u0 * 8] = va0;
            *(uint4*)&sA[nb][r1 * LDS + u1 * 8] = va1;
            *(uint4*)&sB[nb][r0 * LDS + u0 * 8] = vb0;
            *(uint4*)&sB[nb][r1 * LDS + u1 * 8] = vb1;
            __syncthreads();
        }
    }

    // ---- epilogue ----
    if (mode == 1) {
        #pragma unroll
        for (int mi = 0; mi < 2; mi++) {
            #pragma unroll
            for (int h = 0; h < 2; h++) {
                const int row = bm + wm * 32 + mi * 16 + (l >> 2) + h * 8;
                float rs = 0.0f;
                #pragma unroll
                for (int ni = 0; ni < 8; ni++) {
                    const int col = bn + wn * 64 + ni * 8 + (l & 3) * 2;
                    float v0 = acc[mi][ni][h * 2 + 0];
                    float v1 = acc[mi][ni][h * 2 + 1];
                    float e0 = (col     < C_CLS) ? __expf(v0 * NORMF) : 0.0f;
                    float e1 = (col + 1 < C_CLS) ? __expf(v1 * NORMF) : 0.0f;
                    __nv_bfloat162 h2 = __float22bfloat162_rn(make_float2(e0, e1));
                    *(uint32_t*)&g_Ebf[(size_t)row * KPAD + col] =
                        *reinterpret_cast<uint32_t*>(&h2);
                    rs += __bfloat162float(h2.x) + __bfloat162float(h2.y);
                }
                rs += __shfl_xor_sync(0xFFFFFFFFu, rs, 1);
                rs += __shfl_xor_sync(0xFFFFFFFFu, rs, 2);
                if ((l & 3) == 0) atomicAdd(&g_rowsum[row], rs);
            }
        }
    } else {
        #pragma unroll
        for (int mi = 0; mi < 2; mi++) {
            #pragma unroll
            for (int h = 0; h < 2; h++) {
                const int row = bm + wm * 32 + mi * 16 + (l >> 2) + h * 8;
                const float inv = 1.0f / g_rowsum[row];
                const float* pvrow = p_vlm + (size_t)row * C_CLS;
                float*       orow  = out   + (size_t)row * C_CLS;
                #pragma unroll
                for (int ni = 0; ni < 8; ni++) {
                    const int col = bn + wn * 64 + ni * 8 + (l & 3) * 2;
                    #pragma unroll
                    for (int e = 0; e < 2; e++) {
                        int n = col + e;
                        if (n < C_CLS) {
                            float pt  = acc[mi][ni][h * 2 + e] * inv;
                            float pv  = __ldg(pvrow + n);
                            float eut = __expf(pt * __logf(pt + EPSU));
                            float euv = __expf(pv * __logf(pv + EPSU));
                            orow[n] = (eut * pt + euv * pv) / (eut + euv);
                        }
                    }
                }
            }
        }
    }
}

// ---------------------------------------------------------------------------
extern "C" void kernel_launch(void* const* d_in, const int* in_sizes, int n_in,
                              void* d_out, int out_size) {
    const float* p_tar = (const float*)d_in[0];
    const float* p_vlm = (const float*)d_in[1];
    const float* alpha = (const float*)d_in[2];
    const float* bank  = (const float*)d_in[3];
    float* out      = (float*)d_out;                       // p_mix [B,C]
    float* out_bank = out + (size_t)B_ROWS * C_CLS;        // bank_new [C,C]

    zero_kernel<<<(C_CLS * C_CLS + 255) / 256, 256>>>();
    convA_kernel<<<(B_ROWS * KPAD + 255) / 256, 256>>>(p_tar);
    convB_kernel<<<(KPAD * KPAD + 255) / 256, 256>>>(bank);
    argmax_kernel<<<B_ROWS / 8, 256>>>(p_tar, p_vlm);
    scatter_kernel<<<B_ROWS, 128>>>(p_tar);
    bank_kernel<<<(C_CLS * C_CLS + 255) / 256, 256>>>(bank, alpha, out_bank);

    dim3 gg(8, 256);  // 8 n-tiles of 128, 256 m-tiles of 128
    gemm_mma<<<gg, 256>>>(nullptr, nullptr, 1);
    gemm_mma<<<gg, 256>>>(p_vlm, out, 2);
}